// round 16
// baseline (speedup 1.0000x reference)
#include <cuda_runtime.h>
#include <cuda_bf16.h>
#include <math.h>
#include <stdint.h>

// Problem constants
#define Bc   2
#define Lc   2048
#define Dc   1024
#define Hc   16
#define HDc  64
#define Mtot (Bc*Lc)      // 4096
#define BHL  (Bc*Hc*Lc)   // 65536

typedef unsigned long long ull;

// ---- scratch (device globals: allocation-free, graph-capturable) ----
__device__ float  g_q[(size_t)BHL*HDc];      // fp32 QKV-gemm out (pre-rotary)
__device__ float  g_k[(size_t)BHL*HDc];
__device__ float  g_x[(size_t)Mtot*Dc];      // pre-LN
__device__ float2 g_cs[BHL];                 // (cos phi, sin phi)
// packed bf16 tensors (16B aligned via uint4)
__device__ uint4  g_hsh[(size_t)Mtot*Dc/8];  // hidden_states bf16
__device__ uint4  g_wqh[(size_t)Dc*Dc/8];    // weights bf16
__device__ uint4  g_wkh[(size_t)Dc*Dc/8];
__device__ uint4  g_wvh[(size_t)Dc*Dc/8];
__device__ uint4  g_woh[(size_t)Dc*Dc/8];
__device__ uint4  g_qh[(size_t)BHL*HDc/8];   // [bh][l][hd/2 u32] (q*0.125, rotated)
__device__ uint4  g_kh[(size_t)BHL*HDc/8];   // [bh][l][hd/2 u32]
__device__ uint4  g_vth[(size_t)BHL*HDc/8];  // [bh][d][Lc/2 u32] (V transposed)
__device__ uint4  g_ctxh[(size_t)Mtot*Dc/8]; // [B,L,D/2 u32]

// ---- helpers ----
__device__ __forceinline__ uint32_t pkbf2(float lo, float hi) {
    __nv_bfloat162 h = __float22bfloat162_rn(make_float2(lo, hi));
    return *(uint32_t*)&h;
}
__device__ __forceinline__ void mma_bf16(float* c, const uint32_t* a,
                                         uint32_t b0, uint32_t b1)
{
    asm volatile(
        "mma.sync.aligned.m16n8k16.row.col.f32.bf16.bf16.f32 "
        "{%0,%1,%2,%3}, {%4,%5,%6,%7}, {%8,%9}, {%0,%1,%2,%3};"
        : "+f"(c[0]), "+f"(c[1]), "+f"(c[2]), "+f"(c[3])
        : "r"(a[0]), "r"(a[1]), "r"(a[2]), "r"(a[3]), "r"(b0), "r"(b1));
}
__device__ __forceinline__ uint32_t smem_u32(const void* p) {
    return (uint32_t)__cvta_generic_to_shared(p);
}
__device__ __forceinline__ void ldsm_x4(uint32_t* r, uint32_t addr) {
    asm volatile("ldmatrix.sync.aligned.m8n8.x4.shared.b16 {%0,%1,%2,%3}, [%4];"
                 : "=r"(r[0]), "=r"(r[1]), "=r"(r[2]), "=r"(r[3]) : "r"(addr));
}
__device__ __forceinline__ void cpa16(uint32_t dst, const void* src) {
    asm volatile("cp.async.ca.shared.global [%0], [%1], 16;\n" :: "r"(dst), "l"(src));
}
// packed f32x2
__device__ __forceinline__ ull pk2(float lo, float hi) {
    ull r; asm("mov.b64 %0, {%1, %2};" : "=l"(r) : "f"(lo), "f"(hi)); return r;
}
__device__ __forceinline__ float2 upk2(ull v) {
    float2 r; asm("mov.b64 {%0, %1}, %2;" : "=f"(r.x), "=f"(r.y) : "l"(v)); return r;
}
__device__ __forceinline__ ull mulfma2(ull x, ull cx, ull y, ull cy) {
    ull t;
    asm("mul.rn.f32x2 %0, %1, %2;" : "=l"(t) : "l"(y), "l"(cy));
    asm("fma.rn.f32x2 %0, %1, %2, %0;" : "+l"(t) : "l"(x), "l"(cx));
    return t;
}
__device__ __forceinline__ float ex2f(float x) {
    float r; asm("ex2.approx.ftz.f32 %0, %1;" : "=f"(r) : "f"(x)); return r;
}
#define LOG2E 1.442695040888963f

// ============================================================
// fp32 -> packed bf16 conversion (hs + 4 weight matrices).
// ============================================================
__global__ __launch_bounds__(256)
void conv_kernel(const float* __restrict__ hs,
                 const float* __restrict__ Wq, const float* __restrict__ Wk,
                 const float* __restrict__ Wv, const float* __restrict__ Wo)
{
    const int y = blockIdx.y;
    const float* src; uint32_t* dst; int n4;
    if (y == 0)      { src = hs; dst = (uint32_t*)g_hsh; n4 = Mtot*Dc/4; }
    else if (y == 1) { src = Wq; dst = (uint32_t*)g_wqh; n4 = Dc*Dc/4; }
    else if (y == 2) { src = Wk; dst = (uint32_t*)g_wkh; n4 = Dc*Dc/4; }
    else if (y == 3) { src = Wv; dst = (uint32_t*)g_wvh; n4 = Dc*Dc/4; }
    else             { src = Wo; dst = (uint32_t*)g_woh; n4 = Dc*Dc/4; }
    const int idx = blockIdx.x * blockDim.x + threadIdx.x;
    if (idx >= n4) return;
    float4 v = ((const float4*)src)[idx];
    ((uint2*)dst)[idx] = make_uint2(pkbf2(v.x, v.y), pkbf2(v.z, v.w));
}

// ============================================================
// bf16 tile GEMM: pre-packed bf16 operands, cp.async double-buffer,
// ldmatrix fragments. (unchanged from round 15)
// ============================================================
template<int MODE>
__global__ __launch_bounds__(256)
void gemm_kernel(const float* __restrict__ bias0,
                 const float* __restrict__ bias1,
                 const float* __restrict__ bias2,
                 const float* __restrict__ residual)
{
    const uint32_t* Asrc; const uint32_t* Wsrc; const float* bias;
    const int z = (MODE == 0) ? blockIdx.z : 0;
    if (MODE == 0) {
        Asrc = (const uint32_t*)g_hsh;
        Wsrc = (z == 0) ? (const uint32_t*)g_wqh
             : (z == 1) ? (const uint32_t*)g_wkh : (const uint32_t*)g_wvh;
        bias = (z == 0) ? bias0 : (z == 1) ? bias1 : bias2;
    } else {
        Asrc = (const uint32_t*)g_ctxh;
        Wsrc = (const uint32_t*)g_woh;
        bias = bias0;
    }

    __shared__ uint32_t Au[2][128][20];
    __shared__ uint32_t Wu[2][128][20];

    const int tid  = threadIdx.x;
    const int lane = tid & 31;
    const int wid  = tid >> 5;
    const int g    = lane >> 2, tg = lane & 3;
    const int warpM = wid & 1, warpN = wid >> 1;
    const int m0 = blockIdx.y * 128;
    const int n0 = blockIdx.x * 128;

    const int a_lr = lane & 15;
    const int a_lc = (lane >> 4) << 2;
    const int b_lr = ((lane >> 4) << 3) + (lane & 7);
    const int b_lc = ((lane >> 3) & 1) << 2;

    const uint32_t* Abase = Asrc + (size_t)m0 * (Dc/2);
    const uint32_t* Wbase = Wsrc + (size_t)n0 * (Dc/2);

#define G_STAGE(k0_, buf_) do {                                                \
        _Pragma("unroll")                                                      \
        for (int i_ = 0; i_ < 2; i_++) {                                       \
            const int c_ = tid + i_ * 256;                                     \
            const int r_ = c_ >> 2, c4_ = (c_ & 3) * 4;                        \
            cpa16(smem_u32(&Au[buf_][r_][c4_]),                                \
                  Abase + (size_t)r_ * (Dc/2) + ((k0_) >> 1) + c4_);           \
            cpa16(smem_u32(&Wu[buf_][r_][c4_]),                                \
                  Wbase + (size_t)r_ * (Dc/2) + ((k0_) >> 1) + c4_);           \
        }                                                                      \
        asm volatile("cp.async.commit_group;\n" ::);                           \
    } while (0)

    float acc[4][4][4];
    #pragma unroll
    for (int mt = 0; mt < 4; mt++)
        #pragma unroll
        for (int nt = 0; nt < 4; nt++)
            #pragma unroll
            for (int i = 0; i < 4; i++) acc[mt][nt][i] = 0.f;

    G_STAGE(0, 0);
    asm volatile("cp.async.wait_group 0;\n" ::);
    __syncthreads();

    int cur = 0;
    for (int k0 = 0; k0 < Dc; k0 += 32) {
        const bool more = (k0 + 32 < Dc);
        if (more) G_STAGE(k0 + 32, cur ^ 1);

        #pragma unroll
        for (int ks = 0; ks < 2; ks++) {
            uint32_t af[4][4], bfr[2][4];
            #pragma unroll
            for (int mt = 0; mt < 4; mt++)
                ldsm_x4(af[mt], smem_u32(&Au[cur][warpM*64 + mt*16 + a_lr][ks*8 + a_lc]));
            #pragma unroll
            for (int ntp = 0; ntp < 2; ntp++)
                ldsm_x4(bfr[ntp], smem_u32(&Wu[cur][warpN*32 + ntp*16 + b_lr][ks*8 + b_lc]));
            #pragma unroll
            for (int mt = 0; mt < 4; mt++)
                #pragma unroll
                for (int nt = 0; nt < 4; nt++)
                    mma_bf16(acc[mt][nt], af[mt], bfr[nt>>1][(nt&1)*2], bfr[nt>>1][(nt&1)*2+1]);
        }

        if (more) asm volatile("cp.async.wait_group 0;\n" ::);
        __syncthreads();
        cur ^= 1;
    }
#undef G_STAGE

    // epilogue
    #pragma unroll
    for (int mt = 0; mt < 4; mt++) {
        const int mA = m0 + warpM * 64 + mt * 16 + g;
        #pragma unroll
        for (int nt = 0; nt < 4; nt++) {
            const int n = n0 + warpN * 32 + nt * 8 + 2 * tg;
            const float b0v = bias[n], b1v = bias[n + 1];
            #pragma unroll
            for (int rh = 0; rh < 2; rh++) {
                const int m = mA + rh * 8;
                float v0 = acc[mt][nt][rh * 2]     + b0v;
                float v1 = acc[mt][nt][rh * 2 + 1] + b1v;
                if (MODE == 0) {
                    const int bb = m >> 11;
                    const int l  = m & (Lc - 1);
                    const int h  = n >> 6;
                    const int d  = n & 63;
                    if (z == 2) {
                        __nv_bfloat16* vb = (__nv_bfloat16*)g_vth +
                            (((size_t)bb*Hc + h)*HDc + d)*Lc + l;
                        vb[0]  = __float2bfloat16_rn(v0);
                        vb[Lc] = __float2bfloat16_rn(v1);
                    } else {
                        float* out = (z == 0) ? g_q : g_k;
                        *(float2*)&out[(((size_t)bb*Hc + h)*Lc + l)*HDc + d] =
                            make_float2(v0, v1);
                    }
                } else {
                    const float2 rr = *(const float2*)&residual[(size_t)m*Dc + n];
                    *(float2*)&g_x[(size_t)m*Dc + n] = make_float2(v0 + rr.x, v1 + rr.y);
                }
            }
        }
    }
}

// ============================================================
// Rotary: fp32 in (g_q/g_k), packed-bf16 out + cos/sin table.
// ============================================================
__global__ __launch_bounds__(256)
void rotary_kernel(const float* __restrict__ phi)
{
    const int rest = blockIdx.x * blockDim.x + threadIdx.x;  // (b*H+h)*L + l
    if (rest >= BHL) return;
    const int l  = rest & (Lc - 1);
    const int bh = rest >> 11;
    const int h  = bh & (Hc - 1);
    const int b  = bh >> 4;

    const float p = phi[((size_t)b*Lc + l)*Hc + h];
    const float c = cosf(p);
    const float s = sinf(p);
    g_cs[rest] = make_float2(c, s);

    {
        const float4* qp = (const float4*)(g_q + (size_t)rest * HDc);
        float x[64];
        #pragma unroll
        for (int i = 0; i < 16; i++) *(float4*)&x[i*4] = qp[i];
        float r[64];
        #pragma unroll
        for (int d = 0; d < 32; d++) {
            r[d]      = (x[d] * c - x[d + 32] * s) * 0.125f;
            r[d + 32] = (x[d + 32] * c + x[d] * s) * 0.125f;
        }
        uint32_t* qd = (uint32_t*)g_qh + (size_t)rest * 32;
        #pragma unroll
        for (int i = 0; i < 32; i++) qd[i] = pkbf2(r[2*i], r[2*i + 1]);
    }
    {
        const float4* kp = (const float4*)(g_k + (size_t)rest * HDc);
        float x[64];
        #pragma unroll
        for (int i = 0; i < 16; i++) *(float4*)&x[i*4] = kp[i];
        float r[64];
        #pragma unroll
        for (int d = 0; d < 32; d++) {
            r[d]      = x[d] * c - x[d + 32] * s;
            r[d + 32] = x[d + 32] * c + x[d] * s;
        }
        uint32_t* kd = (uint32_t*)g_kh + (size_t)rest * 32;
        #pragma unroll
        for (int i = 0; i < 32; i++) kd[i] = pkbf2(r[2*i], r[2*i + 1]);
    }
}

// ============================================================
// bf16 tensor-core flash attention, v4:
//  - q-block 128 rows, 8 warps (256 thr), 16 rows/warp (per-warp math
//    identical to v3) -> K/V tiles + cs/am staged once per 128 q rows
//    (halves cp.async/STS + table traffic per q-row; shared pipe was
//    the 80.8% binder)
//  - dynamic smem (55.5 KB): Qs[128][36] | Ku[2][64][36] | Vu[2][64][36]
//    | cskx/csky/am2 [2][64]
// grid (Lc/128, Hc, Bc).
// ============================================================
#define ONES_BF2 0x3F803F80u
#define ATTN_SMEM (128*36*4 + 2*64*36*4 + 2*64*36*4 + 3*2*64*4)

__global__ __launch_bounds__(256)
void attn_kernel(const float* __restrict__ amask)
{
    extern __shared__ __align__(16) char dynsm[];
    uint32_t (*Qs)[36]     = reinterpret_cast<uint32_t(*)[36]>(dynsm);
    uint32_t (*Ku)[64][36] = reinterpret_cast<uint32_t(*)[64][36]>(dynsm + 128*36*4);
    uint32_t (*Vu)[64][36] = reinterpret_cast<uint32_t(*)[64][36]>(dynsm + 128*36*4 + 2*64*36*4);
    float* cskx = (float*)(dynsm + 128*36*4 + 4*64*36*4);   // [2][64]
    float* csky = cskx + 2*64;                               // [2][64]
    float* am2  = csky + 2*64;                               // [2][64]

    const int tid  = threadIdx.x;
    const int lane = tid & 31;
    const int warp = tid >> 5;
    const int g    = lane >> 2, tg = lane & 3;

    const int a_lr = lane & 15;
    const int a_lc = (lane >> 4) << 2;
    const int b_lr = ((lane >> 4) << 3) + (lane & 7);
    const int b_lc = ((lane >> 3) & 1) << 2;

    const int b  = blockIdx.z;
    const int h  = blockIdx.y;
    const int q0 = blockIdx.x * 128;
    const int bh = b * Hc + h;
    const size_t bhL = (size_t)bh * Lc;

    const uint32_t* qb = (const uint32_t*)g_qh  + bhL * 32;
    const uint32_t* kb = (const uint32_t*)g_kh  + bhL * 32;
    const uint32_t* vb = (const uint32_t*)g_vth + (size_t)bh * HDc * (Lc/2);

    const int row  = tid >> 1;      // 0..127 ; warp w stages rows [16w,16w+16)
    const int half = tid & 1;

    // --- stage Q tile (already bf16): 128 rows ---
    {
        const uint32_t* src = qb + (size_t)(q0 + row) * 32 + half * 16;
        *(uint4*)&Qs[row][half * 16]      = *(const uint4*)(src);
        *(uint4*)&Qs[row][half * 16 + 4]  = *(const uint4*)(src + 4);
        *(uint4*)&Qs[row][half * 16 + 8]  = *(const uint4*)(src + 8);
        *(uint4*)&Qs[row][half * 16 + 12] = *(const uint4*)(src + 12);
    }
    __syncwarp();

    uint32_t qa[4][4];
    #pragma unroll
    for (int ks = 0; ks < 4; ks++)
        ldsm_x4(qa[ks], smem_u32(&Qs[warp*16 + a_lr][ks*8 + a_lc]));

    const int qrow = warp * 16 + g;
    const float2 csq0 = g_cs[bhL + q0 + qrow];
    const float2 csq1 = g_cs[bhL + q0 + qrow + 8];
    const ull cq0x = pk2(csq0.x, csq0.x), cq0y = pk2(csq0.y, csq0.y);
    const ull cq1x = pk2(csq1.x, csq1.x), cq1y = pk2(csq1.y, csq1.y);
    const int qg0 = q0 + qrow, qg1 = q0 + qrow + 8;

    // K/V tile: 64 keys x 32 u32 = 512 16B chunks each; 256 thr -> 2 per thread
#define STAGE_KV(kt_, buf_) do {                                              \
        _Pragma("unroll")                                                     \
        for (int i_ = 0; i_ < 2; i_++) {                                      \
            const int c_ = tid + i_ * 256;                                    \
            const int r_ = c_ >> 3, c4_ = (c_ & 7) * 4;                       \
            cpa16(smem_u32(&Ku[buf_][r_][c4_]),                               \
                  kb + (size_t)((kt_) + r_) * 32 + c4_);                      \
            cpa16(smem_u32(&Vu[buf_][r_][c4_]),                               \
                  vb + (size_t)r_ * (Lc/2) + ((kt_) >> 1) + c4_);             \
        }                                                                     \
        asm volatile("cp.async.commit_group;\n" ::);                          \
    } while (0)
#define STAGE_CSAM(kt_, buf_) do {                                            \
        if (tid < 64) {                                                       \
            float2 cs_ = g_cs[bhL + (kt_) + tid];                             \
            cskx[(buf_)*64 + tid] = cs_.x;                                    \
            csky[(buf_)*64 + tid] = cs_.y;                                    \
            am2[(buf_)*64 + tid]  = amask[(size_t)b * Lc + (kt_) + tid] * LOG2E; \
        }                                                                     \
    } while (0)

    STAGE_KV(0, 0);
    STAGE_CSAM(0, 0);
    asm volatile("cp.async.wait_group 0;\n" ::);
    __syncthreads();

    float lacc[4] = {0.f, 0.f, 0.f, 0.f};
    float oacc[8][4];
    #pragma unroll
    for (int nt = 0; nt < 8; nt++)
        #pragma unroll
        for (int i = 0; i < 4; i++) oacc[nt][i] = 0.f;

    int cur = 0;
    for (int kt = 0; kt < Lc; kt += 64) {
        const bool more = (kt + 64 < Lc);
        if (more) {
            STAGE_KV(kt + 64, cur ^ 1);
            STAGE_CSAM(kt + 64, cur ^ 1);
        }

        // --- scores: S[16 x 64] per warp ---
        float sacc[8][4];
        #pragma unroll
        for (int nt = 0; nt < 8; nt++)
            #pragma unroll
            for (int i = 0; i < 4; i++) sacc[nt][i] = 0.f;
        #pragma unroll
        for (int ks = 0; ks < 4; ks++) {
            #pragma unroll
            for (int ntp = 0; ntp < 4; ntp++) {
                uint32_t kb4[4];
                ldsm_x4(kb4, smem_u32(&Ku[cur][ntp*16 + b_lr][ks*8 + b_lc]));
                mma_bf16(sacc[2*ntp],     qa[ks], kb4[0], kb4[1]);
                mma_bf16(sacc[2*ntp + 1], qa[ks], kb4[2], kb4[3]);
            }
        }

        // --- mask + fixed-base exp (fp32, packed dc, P in registers) ---
        #pragma unroll
        for (int nt = 0; nt < 8; nt++) {
            const int c0 = nt * 8 + 2 * tg;
            const ull X = *(const ull*)&cskx[cur*64 + c0];   // (ck0x, ck1x)
            const ull Y = *(const ull*)&csky[cur*64 + c0];   // (ck0y, ck1y)
            const float2 d0 = upk2(mulfma2(X, cq0x, Y, cq0y));
            const float2 d1 = upk2(mulfma2(X, cq1x, Y, cq1y));
            const float2 aa = *(const float2*)&am2[cur*64 + c0];

            const float p0 = (d0.x < -0.7f) ? 0.f : ex2f(fmaf(sacc[nt][0], LOG2E, aa.x));
            const float p1 = (d0.y < -0.7f) ? 0.f : ex2f(fmaf(sacc[nt][1], LOG2E, aa.y));
            const float p2 = (d1.x < -0.7f) ? 0.f : ex2f(fmaf(sacc[nt][2], LOG2E, aa.x));
            const float p3 = (d1.y < -0.7f) ? 0.f : ex2f(fmaf(sacc[nt][3], LOG2E, aa.y));
            sacc[nt][0] = p0; sacc[nt][1] = p1;
            sacc[nt][2] = p2; sacc[nt][3] = p3;
        }

        // --- PV: O += P @ V ; lsum += P @ 1 ---
        #pragma unroll
        for (int ks = 0; ks < 4; ks++) {
            uint32_t pa[4];
            pa[0] = pkbf2(sacc[2*ks    ][0], sacc[2*ks    ][1]);
            pa[1] = pkbf2(sacc[2*ks    ][2], sacc[2*ks    ][3]);
            pa[2] = pkbf2(sacc[2*ks + 1][0], sacc[2*ks + 1][1]);
            pa[3] = pkbf2(sacc[2*ks + 1][2], sacc[2*ks + 1][3]);
            #pragma unroll
            for (int ntp = 0; ntp < 4; ntp++) {
                uint32_t vb4[4];
                ldsm_x4(vb4, smem_u32(&Vu[cur][ntp*16 + b_lr][ks*8 + b_lc]));
                mma_bf16(oacc[2*ntp],     pa, vb4[0], vb4[1]);
                mma_bf16(oacc[2*ntp + 1], pa, vb4[2], vb4[3]);
            }
            mma_bf16(lacc, pa, ONES_BF2, ONES_BF2);
        }

        if (more) asm volatile("cp.async.wait_group 0;\n" ::);
        __syncthreads();
        cur ^= 1;
    }

    // --- finalize ---
    const float inv0 = 1.f / lacc[0];
    const float inv1 = 1.f / lacc[2];

    uint32_t* ctxu = (uint32_t*)g_ctxh;
    const size_t base0 = ((size_t)(b * Lc + qg0) * Dc + h * HDc) >> 1;
    const size_t base1 = ((size_t)(b * Lc + qg1) * Dc + h * HDc) >> 1;
    #pragma unroll
    for (int nt = 0; nt < 8; nt++) {
        const int d = nt * 8 + 2 * tg;
        ctxu[base0 + (d >> 1)] = pkbf2(oacc[nt][0] * inv0, oacc[nt][1] * inv0);
        ctxu[base1 + (d >> 1)] = pkbf2(oacc[nt][2] * inv1, oacc[nt][3] * inv1);
    }
#undef STAGE_KV
#undef STAGE_CSAM
}

// ============================================================
// LayerNorm over last dim (1024). one block per row, 256 threads.
// ============================================================
__global__ __launch_bounds__(256)
void ln_kernel(const float* __restrict__ gamma, const float* __restrict__ beta,
               float* __restrict__ out)
{
    const int row = blockIdx.x;
    const int tid = threadIdx.x;
    const float4 v = ((const float4*)(g_x + (size_t)row * Dc))[tid];
    float s  = v.x + v.y + v.z + v.w;
    float sq = v.x*v.x + v.y*v.y + v.z*v.z + v.w*v.w;
    #pragma unroll
    for (int off = 16; off > 0; off >>= 1) {
        s  += __shfl_xor_sync(0xffffffffu, s,  off);
        sq += __shfl_xor_sync(0xffffffffu, sq, off);
    }
    __shared__ float ssum[8], ssq[8];
    const int w = tid >> 5;
    if ((tid & 31) == 0) { ssum[w] = s; ssq[w] = sq; }
    __syncthreads();
    if (tid == 0) {
        float ts = 0.f, tq = 0.f;
        #pragma unroll
        for (int i = 0; i < 8; i++) { ts += ssum[i]; tq += ssq[i]; }
        ssum[0] = ts; ssq[0] = tq;
    }
    __syncthreads();
    const float mean = ssum[0] * (1.f / Dc);
    const float var  = ssq[0]  * (1.f / Dc) - mean * mean;
    const float inv  = rsqrtf(var + 1e-12f);
    const float4 gv = ((const float4*)gamma)[tid];
    const float4 bv = ((const float4*)beta)[tid];
    float4 ov;
    ov.x = (v.x - mean) * inv * gv.x + bv.x;
    ov.y = (v.y - mean) * inv * gv.y + bv.y;
    ov.z = (v.z - mean) * inv * gv.z + bv.z;
    ov.w = (v.w - mean) * inv * gv.w + bv.w;
    ((float4*)out)[(size_t)row * (Dc/4) + tid] = ov;
}

// ============================================================
// launch
// ============================================================
extern "C" void kernel_launch(void* const* d_in, const int* in_sizes, int n_in,
                              void* d_out, int out_size)
{
    const float* hs    = (const float*)d_in[0];
    const float* amask = (const float*)d_in[1];
    const float* phi   = (const float*)d_in[2];
    const float* Wq    = (const float*)d_in[3];
    const float* bq    = (const float*)d_in[4];
    const float* Wk    = (const float*)d_in[5];
    const float* bk    = (const float*)d_in[6];
    const float* Wv    = (const float*)d_in[7];
    const float* bv    = (const float*)d_in[8];
    const float* Wo    = (const float*)d_in[9];
    const float* bo    = (const float*)d_in[10];
    const float* lng   = (const float*)d_in[11];
    const float* lnb   = (const float*)d_in[12];
    float* out = (float*)d_out;

    cudaFuncSetAttribute(attn_kernel,
                         cudaFuncAttributeMaxDynamicSharedMemorySize, ATTN_SMEM);

    // 0) pack hs + weights to bf16
    dim3 gc((Mtot*Dc/4 + 255)/256, 5);
    conv_kernel<<<gc, 256>>>(hs, Wq, Wk, Wv, Wo);

    // 1) QKV projections -> g_q/g_k fp32, g_vth bf16 (transposed)
    dim3 g0(Dc/128, Mtot/128, 3);
    gemm_kernel<0><<<g0, 256>>>(bq, bk, bv, nullptr);

    // 2) rotary -> g_qh/g_kh packed bf16 + cos/sin table
    rotary_kernel<<<BHL/256, 256>>>(phi);

    // 3) attention -> g_ctxh packed bf16 (128-row q blocks, 8 warps)
    dim3 g2(Lc/128, Hc, Bc);
    attn_kernel<<<g2, 256, ATTN_SMEM>>>(amask);

    // 4) output projection + residual -> g_x
    dim3 g3(Dc/128, Mtot/128, 1);
    gemm_kernel<1><<<g3, 256>>>(bo, nullptr, nullptr, hs);

    // 5) layernorm -> d_out
    ln_kernel<<<Mtot, 256>>>(lng, lnb, out);
}

// round 17
// speedup vs baseline: 1.0115x; 1.0115x over previous
#include <cuda_runtime.h>
#include <cuda_bf16.h>
#include <math.h>
#include <stdint.h>

// Problem constants
#define Bc   2
#define Lc   2048
#define Dc   1024
#define Hc   16
#define HDc  64
#define Mtot (Bc*Lc)      // 4096
#define BHL  (Bc*Hc*Lc)   // 65536

typedef unsigned long long ull;

// ---- scratch (device globals: allocation-free, graph-capturable) ----
__device__ float  g_q[(size_t)BHL*HDc];      // fp32 QKV-gemm out (pre-rotary)
__device__ float  g_k[(size_t)BHL*HDc];
__device__ float  g_x[(size_t)Mtot*Dc];      // pre-LN
__device__ float2 g_cs[BHL];                 // (cos phi, sin phi)
// packed bf16 tensors (16B aligned via uint4)
__device__ uint4  g_hsh[(size_t)Mtot*Dc/8];  // hidden_states bf16
__device__ uint4  g_wqh[(size_t)Dc*Dc/8];    // weights bf16
__device__ uint4  g_wkh[(size_t)Dc*Dc/8];
__device__ uint4  g_wvh[(size_t)Dc*Dc/8];
__device__ uint4  g_woh[(size_t)Dc*Dc/8];
__device__ uint4  g_qh[(size_t)BHL*HDc/8];   // [bh][l][hd/2 u32] (q*0.125, rotated)
__device__ uint4  g_kh[(size_t)BHL*HDc/8];   // [bh][l][hd/2 u32]
__device__ uint4  g_vth[(size_t)BHL*HDc/8];  // [bh][d][Lc/2 u32] (V transposed)
__device__ uint4  g_ctxh[(size_t)Mtot*Dc/8]; // [B,L,D/2 u32]

// ---- helpers ----
__device__ __forceinline__ uint32_t pkbf2(float lo, float hi) {
    __nv_bfloat162 h = __float22bfloat162_rn(make_float2(lo, hi));
    return *(uint32_t*)&h;
}
__device__ __forceinline__ void mma_bf16(float* c, const uint32_t* a,
                                         uint32_t b0, uint32_t b1)
{
    asm volatile(
        "mma.sync.aligned.m16n8k16.row.col.f32.bf16.bf16.f32 "
        "{%0,%1,%2,%3}, {%4,%5,%6,%7}, {%8,%9}, {%0,%1,%2,%3};"
        : "+f"(c[0]), "+f"(c[1]), "+f"(c[2]), "+f"(c[3])
        : "r"(a[0]), "r"(a[1]), "r"(a[2]), "r"(a[3]), "r"(b0), "r"(b1));
}
__device__ __forceinline__ uint32_t smem_u32(const void* p) {
    return (uint32_t)__cvta_generic_to_shared(p);
}
__device__ __forceinline__ void ldsm_x4(uint32_t* r, uint32_t addr) {
    asm volatile("ldmatrix.sync.aligned.m8n8.x4.shared.b16 {%0,%1,%2,%3}, [%4];"
                 : "=r"(r[0]), "=r"(r[1]), "=r"(r[2]), "=r"(r[3]) : "r"(addr));
}
__device__ __forceinline__ void cpa16(uint32_t dst, const void* src) {
    asm volatile("cp.async.ca.shared.global [%0], [%1], 16;\n" :: "r"(dst), "l"(src));
}
// packed f32x2
__device__ __forceinline__ ull pk2(float lo, float hi) {
    ull r; asm("mov.b64 %0, {%1, %2};" : "=l"(r) : "f"(lo), "f"(hi)); return r;
}
__device__ __forceinline__ float2 upk2(ull v) {
    float2 r; asm("mov.b64 {%0, %1}, %2;" : "=f"(r.x), "=f"(r.y) : "l"(v)); return r;
}
__device__ __forceinline__ ull mulfma2(ull x, ull cx, ull y, ull cy) {
    ull t;
    asm("mul.rn.f32x2 %0, %1, %2;" : "=l"(t) : "l"(y), "l"(cy));
    asm("fma.rn.f32x2 %0, %1, %2, %0;" : "+l"(t) : "l"(x), "l"(cx));
    return t;
}
__device__ __forceinline__ float ex2f(float x) {
    float r; asm("ex2.approx.ftz.f32 %0, %1;" : "=f"(r) : "f"(x)); return r;
}
#define LOG2E 1.442695040888963f

// ============================================================
// fp32 -> packed bf16 conversion (hs + 4 weight matrices).
// ============================================================
__global__ __launch_bounds__(256)
void conv_kernel(const float* __restrict__ hs,
                 const float* __restrict__ Wq, const float* __restrict__ Wk,
                 const float* __restrict__ Wv, const float* __restrict__ Wo)
{
    const int y = blockIdx.y;
    const float* src; uint32_t* dst; int n4;
    if (y == 0)      { src = hs; dst = (uint32_t*)g_hsh; n4 = Mtot*Dc/4; }
    else if (y == 1) { src = Wq; dst = (uint32_t*)g_wqh; n4 = Dc*Dc/4; }
    else if (y == 2) { src = Wk; dst = (uint32_t*)g_wkh; n4 = Dc*Dc/4; }
    else if (y == 3) { src = Wv; dst = (uint32_t*)g_wvh; n4 = Dc*Dc/4; }
    else             { src = Wo; dst = (uint32_t*)g_woh; n4 = Dc*Dc/4; }
    const int idx = blockIdx.x * blockDim.x + threadIdx.x;
    if (idx >= n4) return;
    float4 v = ((const float4*)src)[idx];
    ((uint2*)dst)[idx] = make_uint2(pkbf2(v.x, v.y), pkbf2(v.z, v.w));
}

// ============================================================
// bf16 tile GEMM, 4-stage cp.async pipeline (dynamic smem 80KB).
// MODE 0: A=g_hsh; z selects Wq/Wk/Wv; z<2 -> fp32 g_q/g_k;
//         z==2 -> bf16 g_vth transposed [bh][d][l].
// MODE 1: A=g_ctxh, W=g_woh; out = g_x = ctx@Wo^T + bo + residual.
// 128x128 tile, K-chunk 32, 256 thr = 8 warps (2m x 4n).
// Empty commit_group every iteration keeps group accounting exact
// through the drain tail (wait_group 2 always releases chunk `cur`).
// ============================================================
#define GSTAGES 4
#define GSM_BYTES (2 * GSTAGES * 128 * 20 * 4)   // Au + Wu

template<int MODE>
__global__ __launch_bounds__(256)
void gemm_kernel(const float* __restrict__ bias0,
                 const float* __restrict__ bias1,
                 const float* __restrict__ bias2,
                 const float* __restrict__ residual)
{
    extern __shared__ __align__(16) char gsm[];
    uint32_t (*Au)[128][20] = reinterpret_cast<uint32_t(*)[128][20]>(gsm);
    uint32_t (*Wu)[128][20] = reinterpret_cast<uint32_t(*)[128][20]>(gsm + GSTAGES*128*20*4);

    const uint32_t* Asrc; const uint32_t* Wsrc; const float* bias;
    const int z = (MODE == 0) ? blockIdx.z : 0;
    if (MODE == 0) {
        Asrc = (const uint32_t*)g_hsh;
        Wsrc = (z == 0) ? (const uint32_t*)g_wqh
             : (z == 1) ? (const uint32_t*)g_wkh : (const uint32_t*)g_wvh;
        bias = (z == 0) ? bias0 : (z == 1) ? bias1 : bias2;
    } else {
        Asrc = (const uint32_t*)g_ctxh;
        Wsrc = (const uint32_t*)g_woh;
        bias = bias0;
    }

    const int tid  = threadIdx.x;
    const int lane = tid & 31;
    const int wid  = tid >> 5;
    const int g    = lane >> 2, tg = lane & 3;
    const int warpM = wid & 1, warpN = wid >> 1;
    const int m0 = blockIdx.y * 128;
    const int n0 = blockIdx.x * 128;

    const int a_lr = lane & 15;
    const int a_lc = (lane >> 4) << 2;
    const int b_lr = ((lane >> 4) << 3) + (lane & 7);
    const int b_lc = ((lane >> 3) & 1) << 2;

    const uint32_t* Abase = Asrc + (size_t)m0 * (Dc/2);
    const uint32_t* Wbase = Wsrc + (size_t)n0 * (Dc/2);

    // stage one 128x32 bf16 chunk of A and W: 512 16B chunks each, 2/thread
#define G_STAGE(k0_, buf_) do {                                                \
        _Pragma("unroll")                                                      \
        for (int i_ = 0; i_ < 2; i_++) {                                       \
            const int c_ = tid + i_ * 256;                                     \
            const int r_ = c_ >> 2, c4_ = (c_ & 3) * 4;                        \
            cpa16(smem_u32(&Au[buf_][r_][c4_]),                                \
                  Abase + (size_t)r_ * (Dc/2) + ((k0_) >> 1) + c4_);           \
            cpa16(smem_u32(&Wu[buf_][r_][c4_]),                                \
                  Wbase + (size_t)r_ * (Dc/2) + ((k0_) >> 1) + c4_);           \
        }                                                                      \
    } while (0)

    float acc[4][4][4];
    #pragma unroll
    for (int mt = 0; mt < 4; mt++)
        #pragma unroll
        for (int nt = 0; nt < 4; nt++)
            #pragma unroll
            for (int i = 0; i < 4; i++) acc[mt][nt][i] = 0.f;

    // prologue: stage chunks 0..2 (3 groups in flight)
    #pragma unroll
    for (int s = 0; s < GSTAGES - 1; s++) {
        G_STAGE(s * 32, s);
        asm volatile("cp.async.commit_group;\n" ::);
    }

    int cur = 0;
    for (int k0 = 0; k0 < Dc; k0 += 32) {
        // release the group containing chunk `cur` (3 in flight -> 2)
        asm volatile("cp.async.wait_group %0;\n" :: "n"(GSTAGES - 2));
        __syncthreads();

        // issue chunk k0+96 into buffer (cur+3)&3 ; empty group if past end
        const int knext = k0 + (GSTAGES - 1) * 32;
        if (knext < Dc) G_STAGE(knext, (cur + GSTAGES - 1) & (GSTAGES - 1));
        asm volatile("cp.async.commit_group;\n" ::);

        // compute on buffer cur
        #pragma unroll
        for (int ks = 0; ks < 2; ks++) {
            uint32_t af[4][4], bfr[2][4];
            #pragma unroll
            for (int mt = 0; mt < 4; mt++)
                ldsm_x4(af[mt], smem_u32(&Au[cur][warpM*64 + mt*16 + a_lr][ks*8 + a_lc]));
            #pragma unroll
            for (int ntp = 0; ntp < 2; ntp++)
                ldsm_x4(bfr[ntp], smem_u32(&Wu[cur][warpN*32 + ntp*16 + b_lr][ks*8 + b_lc]));
            #pragma unroll
            for (int mt = 0; mt < 4; mt++)
                #pragma unroll
                for (int nt = 0; nt < 4; nt++)
                    mma_bf16(acc[mt][nt], af[mt], bfr[nt>>1][(nt&1)*2], bfr[nt>>1][(nt&1)*2+1]);
        }
        cur = (cur + 1) & (GSTAGES - 1);
    }
#undef G_STAGE

    // epilogue
    #pragma unroll
    for (int mt = 0; mt < 4; mt++) {
        const int mA = m0 + warpM * 64 + mt * 16 + g;
        #pragma unroll
        for (int nt = 0; nt < 4; nt++) {
            const int n = n0 + warpN * 32 + nt * 8 + 2 * tg;
            const float b0v = bias[n], b1v = bias[n + 1];
            #pragma unroll
            for (int rh = 0; rh < 2; rh++) {
                const int m = mA + rh * 8;
                float v0 = acc[mt][nt][rh * 2]     + b0v;
                float v1 = acc[mt][nt][rh * 2 + 1] + b1v;
                if (MODE == 0) {
                    const int bb = m >> 11;
                    const int l  = m & (Lc - 1);
                    const int h  = n >> 6;
                    const int d  = n & 63;
                    if (z == 2) {
                        __nv_bfloat16* vb = (__nv_bfloat16*)g_vth +
                            (((size_t)bb*Hc + h)*HDc + d)*Lc + l;
                        vb[0]  = __float2bfloat16_rn(v0);
                        vb[Lc] = __float2bfloat16_rn(v1);
                    } else {
                        float* out = (z == 0) ? g_q : g_k;
                        *(float2*)&out[(((size_t)bb*Hc + h)*Lc + l)*HDc + d] =
                            make_float2(v0, v1);
                    }
                } else {
                    const float2 rr = *(const float2*)&residual[(size_t)m*Dc + n];
                    *(float2*)&g_x[(size_t)m*Dc + n] = make_float2(v0 + rr.x, v1 + rr.y);
                }
            }
        }
    }
}

// ============================================================
// Rotary: fp32 in (g_q/g_k), packed-bf16 out + cos/sin table.
// ============================================================
__global__ __launch_bounds__(256)
void rotary_kernel(const float* __restrict__ phi)
{
    const int rest = blockIdx.x * blockDim.x + threadIdx.x;  // (b*H+h)*L + l
    if (rest >= BHL) return;
    const int l  = rest & (Lc - 1);
    const int bh = rest >> 11;
    const int h  = bh & (Hc - 1);
    const int b  = bh >> 4;

    const float p = phi[((size_t)b*Lc + l)*Hc + h];
    const float c = cosf(p);
    const float s = sinf(p);
    g_cs[rest] = make_float2(c, s);

    {
        const float4* qp = (const float4*)(g_q + (size_t)rest * HDc);
        float x[64];
        #pragma unroll
        for (int i = 0; i < 16; i++) *(float4*)&x[i*4] = qp[i];
        float r[64];
        #pragma unroll
        for (int d = 0; d < 32; d++) {
            r[d]      = (x[d] * c - x[d + 32] * s) * 0.125f;
            r[d + 32] = (x[d + 32] * c + x[d] * s) * 0.125f;
        }
        uint32_t* qd = (uint32_t*)g_qh + (size_t)rest * 32;
        #pragma unroll
        for (int i = 0; i < 32; i++) qd[i] = pkbf2(r[2*i], r[2*i + 1]);
    }
    {
        const float4* kp = (const float4*)(g_k + (size_t)rest * HDc);
        float x[64];
        #pragma unroll
        for (int i = 0; i < 16; i++) *(float4*)&x[i*4] = kp[i];
        float r[64];
        #pragma unroll
        for (int d = 0; d < 32; d++) {
            r[d]      = x[d] * c - x[d + 32] * s;
            r[d + 32] = x[d + 32] * c + x[d] * s;
        }
        uint32_t* kd = (uint32_t*)g_kh + (size_t)rest * 32;
        #pragma unroll
        for (int i = 0; i < 32; i++) kd[i] = pkbf2(r[2*i], r[2*i + 1]);
    }
}

// ============================================================
// bf16 tensor-core flash attention (round-15 version, proven 124.6us):
//  - cp.async double-buffered K/V, 64-row q-block, 4 warps
//  - fixed-base softmax, P in registers
//  - lsum via ones-column mma; diagonal check elided;
//    packed f32x2 dc; exp as FFMA+EX2 with amask pre-scaled by log2e
// grid (Lc/64, Hc, Bc), 128 thr.
// ============================================================
#define ONES_BF2 0x3F803F80u

__global__ __launch_bounds__(128)
void attn_kernel(const float* __restrict__ amask)
{
    __shared__ uint32_t Qs[64][36];
    __shared__ uint32_t Ku[2][64][36];
    __shared__ uint32_t Vu[2][64][36];
    __shared__ float cskx[2][64], csky[2][64], am2[2][64];

    const int tid  = threadIdx.x;
    const int lane = tid & 31;
    const int warp = tid >> 5;
    const int g    = lane >> 2, tg = lane & 3;

    const int a_lr = lane & 15;
    const int a_lc = (lane >> 4) << 2;
    const int b_lr = ((lane >> 4) << 3) + (lane & 7);
    const int b_lc = ((lane >> 3) & 1) << 2;

    const int b  = blockIdx.z;
    const int h  = blockIdx.y;
    const int q0 = blockIdx.x * 64;
    const int bh = b * Hc + h;
    const size_t bhL = (size_t)bh * Lc;

    const uint32_t* qb = (const uint32_t*)g_qh  + bhL * 32;
    const uint32_t* kb = (const uint32_t*)g_kh  + bhL * 32;
    const uint32_t* vb = (const uint32_t*)g_vth + (size_t)bh * HDc * (Lc/2);

    const int row  = tid >> 1;
    const int half = tid & 1;

    // --- stage Q tile (already bf16) ---
    {
        const uint32_t* src = qb + (size_t)(q0 + row) * 32 + half * 16;
        *(uint4*)&Qs[row][half * 16]      = *(const uint4*)(src);
        *(uint4*)&Qs[row][half * 16 + 4]  = *(const uint4*)(src + 4);
        *(uint4*)&Qs[row][half * 16 + 8]  = *(const uint4*)(src + 8);
        *(uint4*)&Qs[row][half * 16 + 12] = *(const uint4*)(src + 12);
    }
    __syncwarp();

    uint32_t qa[4][4];
    #pragma unroll
    for (int ks = 0; ks < 4; ks++)
        ldsm_x4(qa[ks], smem_u32(&Qs[warp*16 + a_lr][ks*8 + a_lc]));

    const int qrow = warp * 16 + g;
    const float2 csq0 = g_cs[bhL + q0 + qrow];
    const float2 csq1 = g_cs[bhL + q0 + qrow + 8];
    const ull cq0x = pk2(csq0.x, csq0.x), cq0y = pk2(csq0.y, csq0.y);
    const ull cq1x = pk2(csq1.x, csq1.x), cq1y = pk2(csq1.y, csq1.y);
    const int qg0 = q0 + qrow, qg1 = q0 + qrow + 8;

#define STAGE_KV(kt_, buf_) do {                                              \
        _Pragma("unroll")                                                     \
        for (int i_ = 0; i_ < 4; i_++) {                                      \
            const int c_ = tid + i_ * 128;                                    \
            const int r_ = c_ >> 3, c4_ = (c_ & 7) * 4;                       \
            cpa16(smem_u32(&Ku[buf_][r_][c4_]),                               \
                  kb + (size_t)((kt_) + r_) * 32 + c4_);                      \
            cpa16(smem_u32(&Vu[buf_][r_][c4_]),                               \
                  vb + (size_t)r_ * (Lc/2) + ((kt_) >> 1) + c4_);             \
        }                                                                     \
        asm volatile("cp.async.commit_group;\n" ::);                          \
    } while (0)
#define STAGE_CSAM(kt_, buf_) do {                                            \
        if (tid < 64) {                                                       \
            float2 cs_ = g_cs[bhL + (kt_) + tid];                             \
            cskx[buf_][tid] = cs_.x;                                          \
            csky[buf_][tid] = cs_.y;                                          \
            am2[buf_][tid]  = amask[(size_t)b * Lc + (kt_) + tid] * LOG2E;    \
        }                                                                     \
    } while (0)

    STAGE_KV(0, 0);
    STAGE_CSAM(0, 0);
    asm volatile("cp.async.wait_group 0;\n" ::);
    __syncthreads();

    float lacc[4] = {0.f, 0.f, 0.f, 0.f};
    float oacc[8][4];
    #pragma unroll
    for (int nt = 0; nt < 8; nt++)
        #pragma unroll
        for (int i = 0; i < 4; i++) oacc[nt][i] = 0.f;

    int cur = 0;
    for (int kt = 0; kt < Lc; kt += 64) {
        const bool more = (kt + 64 < Lc);
        if (more) {
            STAGE_KV(kt + 64, cur ^ 1);
            STAGE_CSAM(kt + 64, cur ^ 1);
        }

        // --- scores: S[16 x 64] per warp ---
        float sacc[8][4];
        #pragma unroll
        for (int nt = 0; nt < 8; nt++)
            #pragma unroll
            for (int i = 0; i < 4; i++) sacc[nt][i] = 0.f;
        #pragma unroll
        for (int ks = 0; ks < 4; ks++) {
            #pragma unroll
            for (int ntp = 0; ntp < 4; ntp++) {
                uint32_t kb4[4];
                ldsm_x4(kb4, smem_u32(&Ku[cur][ntp*16 + b_lr][ks*8 + b_lc]));
                mma_bf16(sacc[2*ntp],     qa[ks], kb4[0], kb4[1]);
                mma_bf16(sacc[2*ntp + 1], qa[ks], kb4[2], kb4[3]);
            }
        }

        // --- mask + fixed-base exp (fp32, packed dc, P in registers) ---
        #pragma unroll
        for (int nt = 0; nt < 8; nt++) {
            const int c0 = nt * 8 + 2 * tg;
            const ull X = *(const ull*)&cskx[cur][c0];
            const ull Y = *(const ull*)&csky[cur][c0];
            const float2 d0 = upk2(mulfma2(X, cq0x, Y, cq0y));
            const float2 d1 = upk2(mulfma2(X, cq1x, Y, cq1y));
            const float2 aa = *(const float2*)&am2[cur][c0];

            const float p0 = (d0.x < -0.7f) ? 0.f : ex2f(fmaf(sacc[nt][0], LOG2E, aa.x));
            const float p1 = (d0.y < -0.7f) ? 0.f : ex2f(fmaf(sacc[nt][1], LOG2E, aa.y));
            const float p2 = (d1.x < -0.7f) ? 0.f : ex2f(fmaf(sacc[nt][2], LOG2E, aa.x));
            const float p3 = (d1.y < -0.7f) ? 0.f : ex2f(fmaf(sacc[nt][3], LOG2E, aa.y));
            sacc[nt][0] = p0; sacc[nt][1] = p1;
            sacc[nt][2] = p2; sacc[nt][3] = p3;
        }

        // --- PV: O += P @ V ; lsum += P @ 1 ---
        #pragma unroll
        for (int ks = 0; ks < 4; ks++) {
            uint32_t pa[4];
            pa[0] = pkbf2(sacc[2*ks    ][0], sacc[2*ks    ][1]);
            pa[1] = pkbf2(sacc[2*ks    ][2], sacc[2*ks    ][3]);
            pa[2] = pkbf2(sacc[2*ks + 1][0], sacc[2*ks + 1][1]);
            pa[3] = pkbf2(sacc[2*ks + 1][2], sacc[2*ks + 1][3]);
            #pragma unroll
            for (int ntp = 0; ntp < 4; ntp++) {
                uint32_t vb4[4];
                ldsm_x4(vb4, smem_u32(&Vu[cur][ntp*16 + b_lr][ks*8 + b_lc]));
                mma_bf16(oacc[2*ntp],     pa, vb4[0], vb4[1]);
                mma_bf16(oacc[2*ntp + 1], pa, vb4[2], vb4[3]);
            }
            mma_bf16(lacc, pa, ONES_BF2, ONES_BF2);
        }

        if (more) asm volatile("cp.async.wait_group 0;\n" ::);
        __syncthreads();
        cur ^= 1;
    }

    // --- finalize ---
    const float inv0 = 1.f / lacc[0];
    const float inv1 = 1.f / lacc[2];

    uint32_t* ctxu = (uint32_t*)g_ctxh;
    const size_t base0 = ((size_t)(b * Lc + qg0) * Dc + h * HDc) >> 1;
    const size_t base1 = ((size_t)(b * Lc + qg1) * Dc + h * HDc) >> 1;
    #pragma unroll
    for (int nt = 0; nt < 8; nt++) {
        const int d = nt * 8 + 2 * tg;
        ctxu[base0 + (d >> 1)] = pkbf2(oacc[nt][0] * inv0, oacc[nt][1] * inv0);
        ctxu[base1 + (d >> 1)] = pkbf2(oacc[nt][2] * inv1, oacc[nt][3] * inv1);
    }
#undef STAGE_KV
#undef STAGE_CSAM
}

// ============================================================
// LayerNorm over last dim (1024). one block per row, 256 threads.
// ============================================================
__global__ __launch_bounds__(256)
void ln_kernel(const float* __restrict__ gamma, const float* __restrict__ beta,
               float* __restrict__ out)
{
    const int row = blockIdx.x;
    const int tid = threadIdx.x;
    const float4 v = ((const float4*)(g_x + (size_t)row * Dc))[tid];
    float s  = v.x + v.y + v.z + v.w;
    float sq = v.x*v.x + v.y*v.y + v.z*v.z + v.w*v.w;
    #pragma unroll
    for (int off = 16; off > 0; off >>= 1) {
        s  += __shfl_xor_sync(0xffffffffu, s,  off);
        sq += __shfl_xor_sync(0xffffffffu, sq, off);
    }
    __shared__ float ssum[8], ssq[8];
    const int w = tid >> 5;
    if ((tid & 31) == 0) { ssum[w] = s; ssq[w] = sq; }
    __syncthreads();
    if (tid == 0) {
        float ts = 0.f, tq = 0.f;
        #pragma unroll
        for (int i = 0; i < 8; i++) { ts += ssum[i]; tq += ssq[i]; }
        ssum[0] = ts; ssq[0] = tq;
    }
    __syncthreads();
    const float mean = ssum[0] * (1.f / Dc);
    const float var  = ssq[0]  * (1.f / Dc) - mean * mean;
    const float inv  = rsqrtf(var + 1e-12f);
    const float4 gv = ((const float4*)gamma)[tid];
    const float4 bv = ((const float4*)beta)[tid];
    float4 ov;
    ov.x = (v.x - mean) * inv * gv.x + bv.x;
    ov.y = (v.y - mean) * inv * gv.y + bv.y;
    ov.z = (v.z - mean) * inv * gv.z + bv.z;
    ov.w = (v.w - mean) * inv * gv.w + bv.w;
    ((float4*)out)[(size_t)row * (Dc/4) + tid] = ov;
}

// ============================================================
// launch
// ============================================================
extern "C" void kernel_launch(void* const* d_in, const int* in_sizes, int n_in,
                              void* d_out, int out_size)
{
    const float* hs    = (const float*)d_in[0];
    const float* amask = (const float*)d_in[1];
    const float* phi   = (const float*)d_in[2];
    const float* Wq    = (const float*)d_in[3];
    const float* bq    = (const float*)d_in[4];
    const float* Wk    = (const float*)d_in[5];
    const float* bk    = (const float*)d_in[6];
    const float* Wv    = (const float*)d_in[7];
    const float* bv    = (const float*)d_in[8];
    const float* Wo    = (const float*)d_in[9];
    const float* bo    = (const float*)d_in[10];
    const float* lng   = (const float*)d_in[11];
    const float* lnb   = (const float*)d_in[12];
    float* out = (float*)d_out;

    cudaFuncSetAttribute(gemm_kernel<0>,
                         cudaFuncAttributeMaxDynamicSharedMemorySize, GSM_BYTES);
    cudaFuncSetAttribute(gemm_kernel<1>,
                         cudaFuncAttributeMaxDynamicSharedMemorySize, GSM_BYTES);

    // 0) pack hs + weights to bf16
    dim3 gc((Mtot*Dc/4 + 255)/256, 5);
    conv_kernel<<<gc, 256>>>(hs, Wq, Wk, Wv, Wo);

    // 1) QKV projections -> g_q/g_k fp32, g_vth bf16 (transposed)
    dim3 g0(Dc/128, Mtot/128, 3);
    gemm_kernel<0><<<g0, 256, GSM_BYTES>>>(bq, bk, bv, nullptr);

    // 2) rotary -> g_qh/g_kh packed bf16 + cos/sin table
    rotary_kernel<<<BHL/256, 256>>>(phi);

    // 3) attention -> g_ctxh packed bf16 (64-row q blocks, round-15 config)
    dim3 g2(Lc/64, Hc, Bc);
    attn_kernel<<<g2, 128>>>(amask);

    // 4) output projection + residual -> g_x
    dim3 g3(Dc/128, Mtot/128, 1);
    gemm_kernel<1><<<g3, 256, GSM_BYTES>>>(bo, nullptr, nullptr, hs);

    // 5) layernorm -> d_out
    ln_kernel<<<Mtot, 256>>>(lng, lnb, out);
}